// round 1
// baseline (speedup 1.0000x reference)
#include <cuda_runtime.h>
#include <cuda_bf16.h>
#include <math_constants.h>
#include <cstdint>

// Problem constants (fixed by dataset)
#define NN     50000
#define EE     800000
#define GG     512
#define IN_DIM 16
#define EDGE_DIM 8
#define HIDC   32
#define OUTD   64
#define HEADS  4
#define D2     (HEADS*HIDC)   // 128

#define SCAN_BLK 1024
#define SCAN_NB  ((NN + SCAN_BLK - 1) / SCAN_BLK)   // 49

// ---------------- device scratch (no runtime allocation allowed) ----------------
__device__ float g_xs[NN * D2];
__device__ float g_xd[NN * D2];
__device__ float g_h1[NN * D2];
__device__ float g_h2[NN * D2];
__device__ float g_h3[NN * HIDC];
__device__ int   g_deg[NN];
__device__ int   g_tmp[SCAN_NB * SCAN_BLK];
__device__ int   g_rowptr[NN + 1];
__device__ int   g_wp[NN];
__device__ int   g_blksum[SCAN_NB + 1];
__device__ int2  g_csr[EE];
__device__ float g_sums[GG * HIDC];
__device__ float g_cnt[GG];

// ---------------- CSR build ----------------
__global__ void zero_kernel() {
    int i = blockIdx.x * blockDim.x + threadIdx.x;
    if (i < NN) g_deg[i] = 0;
    if (i < GG * HIDC) g_sums[i] = 0.f;
    if (i < GG) g_cnt[i] = 0.f;
}

__global__ void hist_kernel(const int* __restrict__ dst) {
    int e = blockIdx.x * blockDim.x + threadIdx.x;
    if (e < EE) atomicAdd(&g_deg[dst[e]], 1);
}

__global__ void scan1_kernel() {
    __shared__ int sm[SCAN_BLK];
    int tid = threadIdx.x;
    int i = blockIdx.x * SCAN_BLK + tid;
    int v = (i < NN) ? g_deg[i] : 0;
    sm[tid] = v;
    __syncthreads();
    for (int o = 1; o < SCAN_BLK; o <<= 1) {
        int t = (tid >= o) ? sm[tid - o] : 0;
        __syncthreads();
        sm[tid] += t;
        __syncthreads();
    }
    g_tmp[blockIdx.x * SCAN_BLK + tid] = sm[tid] - v;   // exclusive within block
    if (tid == SCAN_BLK - 1) g_blksum[blockIdx.x] = sm[tid];
}

__global__ void scan2_kernel() {
    if (threadIdx.x == 0 && blockIdx.x == 0) {
        int run = 0;
        for (int b = 0; b < SCAN_NB; b++) {
            int t = g_blksum[b];
            g_blksum[b] = run;
            run += t;
        }
    }
}

__global__ void scan3_kernel() {
    int i = blockIdx.x * blockDim.x + threadIdx.x;
    if (i < NN) {
        int v = g_tmp[i] + g_blksum[i / SCAN_BLK];
        g_rowptr[i] = v;
        g_wp[i] = v;
    }
    if (i == 0) g_rowptr[NN] = EE;
}

__global__ void scatter_kernel(const int* __restrict__ src, const int* __restrict__ dst) {
    int e = blockIdx.x * blockDim.x + threadIdx.x;
    if (e < EE) {
        int d = dst[e];
        int pos = atomicAdd(&g_wp[d], 1);
        g_csr[pos] = make_int2(src[e], e);
    }
}

// deterministic order within each bucket (insertion sort by edge id)
__global__ void sortcsr_kernel() {
    int n = blockIdx.x * blockDim.x + threadIdx.x;
    if (n >= NN) return;
    int s = g_rowptr[n], e = g_rowptr[n + 1];
    for (int i = s + 1; i < e; i++) {
        int2 key = g_csr[i];
        int j = i - 1;
        while (j >= s && g_csr[j].y > key.y) { g_csr[j + 1] = g_csr[j]; j--; }
        g_csr[j + 1] = key;
    }
}

// ---------------- node linear: xs = x@Ws+bs, xd = x@Wd+bd ----------------
// block = DOUT threads, each block handles TN nodes.
template<int DIN, int DOUT, int TN>
__global__ void node_linear_kernel(const float* __restrict__ x,
                                   const float* __restrict__ Ws, const float* __restrict__ Wd,
                                   const float* __restrict__ bs, const float* __restrict__ bd,
                                   float* __restrict__ xs, float* __restrict__ xd) {
    __shared__ float xsm[TN][DIN];
    const int n0 = blockIdx.x * TN;
    const int tid = threadIdx.x;
    for (int i = tid; i < TN * DIN; i += DOUT) {
        int t = i / DIN, k = i % DIN;
        int n = n0 + t;
        xsm[t][k] = (n < NN) ? x[n * DIN + k] : 0.f;
    }
    __syncthreads();

    float acc_s[TN], acc_d[TN];
#pragma unroll
    for (int t = 0; t < TN; t++) { acc_s[t] = 0.f; acc_d[t] = 0.f; }

#pragma unroll 4
    for (int k = 0; k < DIN; k += 4) {
        float ws0 = Ws[(k + 0) * DOUT + tid], ws1 = Ws[(k + 1) * DOUT + tid];
        float ws2 = Ws[(k + 2) * DOUT + tid], ws3 = Ws[(k + 3) * DOUT + tid];
        float wd0 = Wd[(k + 0) * DOUT + tid], wd1 = Wd[(k + 1) * DOUT + tid];
        float wd2 = Wd[(k + 2) * DOUT + tid], wd3 = Wd[(k + 3) * DOUT + tid];
#pragma unroll
        for (int t = 0; t < TN; t++) {
            float4 xv = *reinterpret_cast<const float4*>(&xsm[t][k]);
            acc_s[t] += xv.x * ws0 + xv.y * ws1 + xv.z * ws2 + xv.w * ws3;
            acc_d[t] += xv.x * wd0 + xv.y * wd1 + xv.z * wd2 + xv.w * wd3;
        }
    }
    float bsv = bs[tid], bdv = bd[tid];
#pragma unroll
    for (int t = 0; t < TN; t++) {
        int n = n0 + t;
        if (n < NN) {
            xs[n * DOUT + tid] = acc_s[t] + bsv;
            xd[n * DOUT + tid] = acc_d[t] + bdv;
        }
    }
}

// ---------------- GATv2 edge aggregation: warp per (node, head) ----------------
template<int H, bool ELU>
__global__ void gat_edge_kernel(const float* __restrict__ xs, const float* __restrict__ xd,
                                const float* __restrict__ edge_attr,
                                const float* __restrict__ We,
                                const float* __restrict__ att,
                                const float* __restrict__ bias,
                                float* __restrict__ out) {
    const int HC = H * 32;
    int w = (blockIdx.x * blockDim.x + threadIdx.x) >> 5;
    int lane = threadIdx.x & 31;
    if (w >= NN * H) return;
    int n = w / H;
    int h = w - n * H;
    int col = h * 32 + lane;

    float we[EDGE_DIM];
#pragma unroll
    for (int k = 0; k < EDGE_DIM; k++) we[k] = We[k * HC + col];
    float attv = att[col];
    float xdv = xd[n * HC + col];

    int start = g_rowptr[n], end = g_rowptr[n + 1];
    float m = -CUDART_INF_F, s = 0.f, acc = 0.f;

    for (int base = start; base < end; base += 32) {
        int cnt = end - base;
        if (cnt > 32) cnt = 32;
        int2 ed = g_csr[base + (lane < cnt ? lane : cnt - 1)];
        for (int j = 0; j < cnt; j++) {
            int src = __shfl_sync(0xffffffffu, ed.x, j);
            int eid = __shfl_sync(0xffffffffu, ed.y, j);
            float xsv = xs[src * HC + col];
            const float4* ap = reinterpret_cast<const float4*>(edge_attr + (size_t)eid * EDGE_DIM);
            float4 a0 = ap[0], a1 = ap[1];
            float ea = a0.x * we[0] + a0.y * we[1] + a0.z * we[2] + a0.w * we[3]
                     + a1.x * we[4] + a1.y * we[5] + a1.z * we[6] + a1.w * we[7];
            float z = xsv + xdv + ea;
            z = (z > 0.f) ? z : 0.2f * z;
            float ev = z * attv;
#pragma unroll
            for (int o = 16; o > 0; o >>= 1) ev += __shfl_xor_sync(0xffffffffu, ev, o);
            float nm = fmaxf(m, ev);
            float sc = __expf(m - nm);          // 0 on first edge (m = -inf)
            float p  = __expf(ev - nm);
            s   = s * sc + p;
            acc = acc * sc + p * xsv;
            m = nm;
        }
    }
    float o = (s > 0.f) ? acc / s : 0.f;
    o += bias[col];
    if (ELU) o = (o > 0.f) ? o : expm1f(o);
    out[n * HC + col] = o;
}

// ---------------- pooling ----------------
__global__ void pool_kernel(const int* __restrict__ batch) {
    int i = blockIdx.x * blockDim.x + threadIdx.x;
    if (i >= NN * HIDC) return;
    int n = i >> 5;
    int c = i & 31;
    int g = batch[n];
    atomicAdd(&g_sums[g * HIDC + c], g_h3[i]);
    if (c == 0) atomicAdd(&g_cnt[g], 1.f);
}

// ---------------- MLP head ----------------
__global__ void mlp_kernel(const float* __restrict__ Wm1, const float* __restrict__ bm1,
                           const float* __restrict__ Wm2, const float* __restrict__ bm2,
                           float* __restrict__ out) {
    __shared__ float emb[HIDC];
    __shared__ float hid[2 * HIDC];
    int g = blockIdx.x;
    int tid = threadIdx.x;   // 64 threads
    if (tid < HIDC) {
        float c = g_cnt[g];
        emb[tid] = g_sums[g * HIDC + tid] / fmaxf(c, 1.f);
    }
    __syncthreads();
    float a = bm1[tid];
#pragma unroll
    for (int k = 0; k < HIDC; k++) a += emb[k] * Wm1[k * (2 * HIDC) + tid];
    hid[tid] = fmaxf(a, 0.f);
    __syncthreads();
    float o = bm2[tid];
#pragma unroll
    for (int k = 0; k < 2 * HIDC; k++) o += hid[k] * Wm2[k * OUTD + tid];
    out[g * OUTD + tid] = o;
}

// ---------------- launch ----------------
extern "C" void kernel_launch(void* const* d_in, const int* in_sizes, int n_in,
                              void* d_out, int out_size) {
    const float* x         = (const float*)d_in[0];
    const int*   edge_src  = (const int*)d_in[1];
    const int*   edge_dst  = (const int*)d_in[2];
    const float* edge_attr = (const float*)d_in[3];
    const int*   batch     = (const int*)d_in[4];
    const float* W1s = (const float*)d_in[5],  *W1d = (const float*)d_in[6],  *W1e = (const float*)d_in[7];
    const float* b1s = (const float*)d_in[8],  *b1d = (const float*)d_in[9];
    const float* att1 = (const float*)d_in[10], *bias1 = (const float*)d_in[11];
    const float* W2s = (const float*)d_in[12], *W2d = (const float*)d_in[13], *W2e = (const float*)d_in[14];
    const float* b2s = (const float*)d_in[15], *b2d = (const float*)d_in[16];
    const float* att2 = (const float*)d_in[17], *bias2 = (const float*)d_in[18];
    const float* W3s = (const float*)d_in[19], *W3d = (const float*)d_in[20], *W3e = (const float*)d_in[21];
    const float* b3s = (const float*)d_in[22], *b3d = (const float*)d_in[23];
    const float* att3 = (const float*)d_in[24], *bias3 = (const float*)d_in[25];
    const float* Wm1 = (const float*)d_in[26], *bm1 = (const float*)d_in[27];
    const float* Wm2 = (const float*)d_in[28], *bm2 = (const float*)d_in[29];
    float* out = (float*)d_out;

    void *p_xs, *p_xd, *p_h1, *p_h2, *p_h3;
    cudaGetSymbolAddress(&p_xs, g_xs);
    cudaGetSymbolAddress(&p_xd, g_xd);
    cudaGetSymbolAddress(&p_h1, g_h1);
    cudaGetSymbolAddress(&p_h2, g_h2);
    cudaGetSymbolAddress(&p_h3, g_h3);
    float* xs = (float*)p_xs; float* xd = (float*)p_xd;
    float* h1 = (float*)p_h1; float* h2 = (float*)p_h2; float* h3 = (float*)p_h3;

    // CSR build
    zero_kernel<<<(NN + 255) / 256, 256>>>();
    hist_kernel<<<(EE + 255) / 256, 256>>>(edge_dst);
    scan1_kernel<<<SCAN_NB, SCAN_BLK>>>();
    scan2_kernel<<<1, 32>>>();
    scan3_kernel<<<(NN + 255) / 256, 256>>>();
    scatter_kernel<<<(EE + 255) / 256, 256>>>(edge_src, edge_dst);
    sortcsr_kernel<<<(NN + 255) / 256, 256>>>();

    const int edge_blocks4 = (NN * HEADS * 32 + 255) / 256;
    const int edge_blocks1 = (NN * 1 * 32 + 255) / 256;

    // Layer 1: 16 -> [4,32]
    node_linear_kernel<IN_DIM, D2, 16><<<(NN + 15) / 16, D2>>>(x, W1s, W1d, b1s, b1d, xs, xd);
    gat_edge_kernel<HEADS, true><<<edge_blocks4, 256>>>(xs, xd, edge_attr, W1e, att1, bias1, h1);

    // Layer 2: 128 -> [4,32]
    node_linear_kernel<D2, D2, 16><<<(NN + 15) / 16, D2>>>(h1, W2s, W2d, b2s, b2d, xs, xd);
    gat_edge_kernel<HEADS, true><<<edge_blocks4, 256>>>(xs, xd, edge_attr, W2e, att2, bias2, h2);

    // Layer 3: 128 -> [1,32]
    node_linear_kernel<D2, HIDC, 16><<<(NN + 15) / 16, HIDC>>>(h2, W3s, W3d, b3s, b3d, xs, xd);
    gat_edge_kernel<1, false><<<edge_blocks1, 256>>>(xs, xd, edge_attr, W3e, att3, bias3, h3);

    // Pool + MLP
    pool_kernel<<<(NN * HIDC + 255) / 256, 256>>>(batch);
    mlp_kernel<<<GG, OUTD>>>(Wm1, bm1, Wm2, bm2, out);
}